// round 6
// baseline (speedup 1.0000x reference)
#include <cuda_runtime.h>

// QuantileLoss: out = mean( concat( (preds[:,:3]-target[:,:3])^2  (3N elems),
//                                   lower (N), lower (N) ) )
// lower = p3>p2 ? 1000 : (p3 > 0.95*t2 ? 0 : (p3-0.95*t2)^2)
// => out = sum_rows( mse_row + 2*lower_row ) / (5*N)
//
// Kernel 1: one resident wave (148 SM x 7 blocks), grid-stride over 4-row
//           units (5 aligned float4 of preds + 3 of target). Block-reduces
//           to fp32, one atomicAdd per block into g_sum. No fences, no
//           counters, no tail code -> minimal regs, max occupancy.
// Kernel 2: <<<1,1>>> reads g_sum, writes mean, resets g_sum for the next
//           graph replay (kernel-boundary ordering makes this deterministic).

#define NROWS 8388608
#define UNITS (NROWS / 4)
#define NBLOCKS 1036            // 148 SMs * 7 blocks: single resident wave
#define NTHREADS 256

__device__ float g_sum = 0.0f;

__device__ __forceinline__ float row_loss(float pc0, float pc1, float pc2, float pc3,
                                          float tc0, float tc1, float tc2) {
    float d0 = pc0 - tc0;
    float d1 = pc1 - tc1;
    float d2 = pc2 - tc2;
    float mse = fmaf(d0, d0, fmaf(d1, d1, d2 * d2));
    float q = tc2 * 0.95f;
    float d = pc3 - q;
    float lower = (pc3 > pc2) ? 1000.0f : ((pc3 > q) ? 0.0f : d * d);
    return fmaf(2.0f, lower, mse);
}

__global__ __launch_bounds__(NTHREADS)
void ql_partial_kernel(const float4* __restrict__ p4,
                       const float4* __restrict__ t4) {
    const int tid = threadIdx.x;
    const int gstride = NBLOCKS * NTHREADS;

    float local = 0.0f;

    for (int u = blockIdx.x * NTHREADS + tid; u < UNITS; u += gstride) {
        const float4* pb = p4 + (size_t)u * 5;   // 4 rows of preds = 5 aligned float4
        float4 p0 = pb[0];
        float4 p1 = pb[1];
        float4 p2 = pb[2];
        float4 p3 = pb[3];
        float4 p4v = pb[4];
        const float4* tb = t4 + (size_t)u * 3;   // 4 rows of target = 3 aligned float4
        float4 t0 = tb[0];
        float4 t1 = tb[1];
        float4 t2 = tb[2];

        // row 0: preds {p0.x,p0.y,p0.z,p0.w}    target {t0.x,t0.y,t0.z}
        float s = row_loss(p0.x, p0.y, p0.z, p0.w, t0.x, t0.y, t0.z);
        // row 1: preds {p1.y,p1.z,p1.w,p2.x}    target {t0.w,t1.x,t1.y}
        s += row_loss(p1.y, p1.z, p1.w, p2.x, t0.w, t1.x, t1.y);
        // row 2: preds {p2.z,p2.w,p3.x,p3.y}    target {t1.z,t1.w,t2.x}
        s += row_loss(p2.z, p2.w, p3.x, p3.y, t1.z, t1.w, t2.x);
        // row 3: preds {p3.w,p4v.x,p4v.y,p4v.z} target {t2.y,t2.z,t2.w}
        s += row_loss(p3.w, p4v.x, p4v.y, p4v.z, t2.y, t2.z, t2.w);

        local += s;
    }

    // ---- block reduce (fp32) ----
    #pragma unroll
    for (int off = 16; off > 0; off >>= 1)
        local += __shfl_down_sync(0xFFFFFFFFu, local, off);

    __shared__ float warp_sums[NTHREADS / 32];
    const int warp = tid >> 5;
    const int lane = tid & 31;
    if (lane == 0) warp_sums[warp] = local;
    __syncthreads();

    if (tid == 0) {
        float bsum = 0.0f;
        #pragma unroll
        for (int w = 0; w < NTHREADS / 32; w++) bsum += warp_sums[w];
        atomicAdd(&g_sum, bsum);   // 1036 fp32 atomics total: negligible
    }
}

__global__ void ql_final_kernel(float* __restrict__ out) {
    // single thread: read total, write mean, reset accumulator for next replay
    double total = (double)g_sum;
    out[0] = (float)(total / (5.0 * (double)NROWS));
    g_sum = 0.0f;
}

extern "C" void kernel_launch(void* const* d_in, const int* in_sizes, int n_in,
                              void* d_out, int out_size) {
    const float4* preds  = (const float4*)d_in[0];   // (N,5) f32, rows 20B, base 16B-aligned
    const float4* target = (const float4*)d_in[1];   // (N,3) f32
    float* out = (float*)d_out;
    (void)in_sizes; (void)n_in; (void)out_size;

    ql_partial_kernel<<<NBLOCKS, NTHREADS>>>(preds, target);
    ql_final_kernel<<<1, 1>>>(out);
}

// round 7
// speedup vs baseline: 1.2142x; 1.2142x over previous
#include <cuda_runtime.h>

// QuantileLoss: out = mean( concat( (preds[:,:3]-target[:,:3])^2  (3N elems),
//                                   lower (N), lower (N) ) )
// lower = p3>p2 ? 1000 : (p3 > 0.95*t2 ? 0 : (p3-0.95*t2)^2)
// => out = sum_rows( mse_row + 2*lower_row ) / (5*N)
//
// Kernel 1: 4096 blocks x 256 thr, EXACTLY 2 four-row units per thread
//           (UNITS = 2^21, gstride = 2^20). Oversubscribed fine-grained
//           blocks -> work-stealing smooths per-SM spread (single-wave
//           config measured 8us slower in R6). Plain store of one fp32
//           partial per block; no atomics, fences, or tail code.
// Kernel 2: 256 threads, float4 loads of the 4096 partials, fp32 lane
//           sums, fp64 only for the final 8-way combine.

#define NROWS 8388608
#define UNITS (NROWS / 4)        // 2^21 four-row units
#define NBLOCKS 4096
#define NTHREADS 256
#define GSTRIDE (NBLOCKS * NTHREADS)   // 2^20 -> exactly 2 units/thread

__device__ float g_block[NBLOCKS];

__device__ __forceinline__ float row_loss(float pc0, float pc1, float pc2, float pc3,
                                          float tc0, float tc1, float tc2) {
    float d0 = pc0 - tc0;
    float d1 = pc1 - tc1;
    float d2 = pc2 - tc2;
    float mse = fmaf(d0, d0, fmaf(d1, d1, d2 * d2));
    float q = tc2 * 0.95f;
    float d = pc3 - q;
    float lower = (pc3 > pc2) ? 1000.0f : ((pc3 > q) ? 0.0f : d * d);
    return fmaf(2.0f, lower, mse);
}

__device__ __forceinline__ float unit_loss(const float4* __restrict__ p4,
                                           const float4* __restrict__ t4,
                                           int u) {
    const float4* pb = p4 + (size_t)u * 5;   // 4 rows of preds = 5 aligned float4
    float4 p0 = pb[0];
    float4 p1 = pb[1];
    float4 p2 = pb[2];
    float4 p3 = pb[3];
    float4 p4v = pb[4];
    const float4* tb = t4 + (size_t)u * 3;   // 4 rows of target = 3 aligned float4
    float4 t0 = tb[0];
    float4 t1 = tb[1];
    float4 t2 = tb[2];

    float s = row_loss(p0.x, p0.y, p0.z, p0.w, t0.x, t0.y, t0.z);
    s += row_loss(p1.y, p1.z, p1.w, p2.x, t0.w, t1.x, t1.y);
    s += row_loss(p2.z, p2.w, p3.x, p3.y, t1.z, t1.w, t2.x);
    s += row_loss(p3.w, p4v.x, p4v.y, p4v.z, t2.y, t2.z, t2.w);
    return s;
}

__global__ __launch_bounds__(NTHREADS)
void ql_partial_kernel(const float4* __restrict__ p4,
                       const float4* __restrict__ t4) {
    const int tid = threadIdx.x;
    const int u0 = blockIdx.x * NTHREADS + tid;

    // exactly two units per thread, fully unrolled
    float local = unit_loss(p4, t4, u0)
                + unit_loss(p4, t4, u0 + GSTRIDE);

    // ---- block reduce (fp32) ----
    #pragma unroll
    for (int off = 16; off > 0; off >>= 1)
        local += __shfl_down_sync(0xFFFFFFFFu, local, off);

    __shared__ float warp_sums[NTHREADS / 32];
    const int warp = tid >> 5;
    const int lane = tid & 31;
    if (lane == 0) warp_sums[warp] = local;
    __syncthreads();

    if (tid == 0) {
        float bsum = 0.0f;
        #pragma unroll
        for (int w = 0; w < NTHREADS / 32; w++) bsum += warp_sums[w];
        g_block[blockIdx.x] = bsum;
    }
}

__global__ __launch_bounds__(NTHREADS)
void ql_final_kernel(float* __restrict__ out) {
    const int tid = threadIdx.x;
    const float4* gb4 = (const float4*)g_block;   // 1024 float4

    float local = 0.0f;
    #pragma unroll
    for (int i = 0; i < 4; i++) {
        float4 v = gb4[tid + i * NTHREADS];
        local += (v.x + v.y) + (v.z + v.w);
    }

    double dsum = (double)local;
    #pragma unroll
    for (int off = 16; off > 0; off >>= 1)
        dsum += __shfl_down_sync(0xFFFFFFFFu, dsum, off);

    __shared__ double dwarp[NTHREADS / 32];
    const int warp = tid >> 5;
    const int lane = tid & 31;
    if (lane == 0) dwarp[warp] = dsum;
    __syncthreads();

    if (tid == 0) {
        double total = 0.0;
        #pragma unroll
        for (int w = 0; w < NTHREADS / 32; w++) total += dwarp[w];
        out[0] = (float)(total / (5.0 * (double)NROWS));
    }
}

extern "C" void kernel_launch(void* const* d_in, const int* in_sizes, int n_in,
                              void* d_out, int out_size) {
    const float4* preds  = (const float4*)d_in[0];   // (N,5) f32, rows 20B, base 16B-aligned
    const float4* target = (const float4*)d_in[1];   // (N,3) f32
    float* out = (float*)d_out;
    (void)in_sizes; (void)n_in; (void)out_size;

    ql_partial_kernel<<<NBLOCKS, NTHREADS>>>(preds, target);
    ql_final_kernel<<<1, NTHREADS>>>(out);
}

// round 8
// speedup vs baseline: 1.2185x; 1.0035x over previous
#include <cuda_runtime.h>

// QuantileLoss: out = mean( concat( (preds[:,:3]-target[:,:3])^2  (3N elems),
//                                   lower (N), lower (N) ) )
// lower = p3>p2 ? 1000 : (p3 > 0.95*t2 ? 0 : (p3-0.95*t2)^2)
// => out = sum_rows( mse_row + 2*lower_row ) / (5*N)
//
// Kernel 1 (unchanged hot path from R7 best): 4096 blocks x 256 thr, exactly
//   2 four-row units per thread, fully unrolled (MLP=16 LDG.128). Each block
//   fp32-atomicAdds its partial into g_sum (4096 same-address L2 atomics over
//   ~40us: free; measured rel_err 2.3e-7 with this scheme in R6).
//   Calls cudaTriggerProgrammaticLaunchCompletion() at entry for PDL.
// Kernel 2: <<<1,1>>> launched with ProgrammaticStreamSerialization so its
//   ~3.9us launch overhead overlaps kernel 1's mainloop. It parks in
//   cudaGridDependencySynchronize(), then reads g_sum, writes the mean, and
//   resets g_sum for the next graph replay (graph edge orders this before
//   the next replay's kernel 1).

#define NROWS 8388608
#define UNITS (NROWS / 4)              // 2^21 four-row units
#define NBLOCKS 4096
#define NTHREADS 256
#define GSTRIDE (NBLOCKS * NTHREADS)   // 2^20 -> exactly 2 units/thread

__device__ float g_sum = 0.0f;

__device__ __forceinline__ float row_loss(float pc0, float pc1, float pc2, float pc3,
                                          float tc0, float tc1, float tc2) {
    float d0 = pc0 - tc0;
    float d1 = pc1 - tc1;
    float d2 = pc2 - tc2;
    float mse = fmaf(d0, d0, fmaf(d1, d1, d2 * d2));
    float q = tc2 * 0.95f;
    float d = pc3 - q;
    float lower = (pc3 > pc2) ? 1000.0f : ((pc3 > q) ? 0.0f : d * d);
    return fmaf(2.0f, lower, mse);
}

__device__ __forceinline__ float unit_loss(const float4* __restrict__ p4,
                                           const float4* __restrict__ t4,
                                           int u) {
    const float4* pb = p4 + (size_t)u * 5;   // 4 rows of preds = 5 aligned float4
    float4 p0 = pb[0];
    float4 p1 = pb[1];
    float4 p2 = pb[2];
    float4 p3 = pb[3];
    float4 p4v = pb[4];
    const float4* tb = t4 + (size_t)u * 3;   // 4 rows of target = 3 aligned float4
    float4 t0 = tb[0];
    float4 t1 = tb[1];
    float4 t2 = tb[2];

    float s = row_loss(p0.x, p0.y, p0.z, p0.w, t0.x, t0.y, t0.z);
    s += row_loss(p1.y, p1.z, p1.w, p2.x, t0.w, t1.x, t1.y);
    s += row_loss(p2.z, p2.w, p3.x, p3.y, t1.z, t1.w, t2.x);
    s += row_loss(p3.w, p4v.x, p4v.y, p4v.z, t2.y, t2.z, t2.w);
    return s;
}

__global__ __launch_bounds__(NTHREADS)
void ql_partial_kernel(const float4* __restrict__ p4,
                       const float4* __restrict__ t4) {
    // PDL: let the dependent finalize kernel start its launch setup early.
    cudaTriggerProgrammaticLaunchCompletion();

    const int tid = threadIdx.x;
    const int u0 = blockIdx.x * NTHREADS + tid;

    // exactly two units per thread, fully unrolled
    float local = unit_loss(p4, t4, u0)
                + unit_loss(p4, t4, u0 + GSTRIDE);

    // ---- block reduce (fp32) ----
    #pragma unroll
    for (int off = 16; off > 0; off >>= 1)
        local += __shfl_down_sync(0xFFFFFFFFu, local, off);

    __shared__ float warp_sums[NTHREADS / 32];
    const int warp = tid >> 5;
    const int lane = tid & 31;
    if (lane == 0) warp_sums[warp] = local;
    __syncthreads();

    if (tid == 0) {
        float bsum = 0.0f;
        #pragma unroll
        for (int w = 0; w < NTHREADS / 32; w++) bsum += warp_sums[w];
        atomicAdd(&g_sum, bsum);   // 4096 same-address fp32 atomics: negligible
    }
}

__global__ void ql_final_kernel(float* __restrict__ out) {
    // Wait until the partial kernel has fully completed and its memory
    // (all g_sum atomics) is visible.
    cudaGridDependencySynchronize();
    double total = (double)g_sum;
    out[0] = (float)(total / (5.0 * (double)NROWS));
    g_sum = 0.0f;   // reset for the next graph replay
}

extern "C" void kernel_launch(void* const* d_in, const int* in_sizes, int n_in,
                              void* d_out, int out_size) {
    const float4* preds  = (const float4*)d_in[0];   // (N,5) f32, rows 20B, base 16B-aligned
    const float4* target = (const float4*)d_in[1];   // (N,3) f32
    float* out = (float*)d_out;
    (void)in_sizes; (void)n_in; (void)out_size;

    ql_partial_kernel<<<NBLOCKS, NTHREADS>>>(preds, target);

    // Finalize with programmatic dependent launch: overlaps launch latency
    // with the partial kernel's execution.
    cudaLaunchConfig_t cfg = {};
    cfg.gridDim  = dim3(1, 1, 1);
    cfg.blockDim = dim3(1, 1, 1);
    cfg.dynamicSmemBytes = 0;
    cfg.stream = 0;
    cudaLaunchAttribute attrs[1];
    attrs[0].id = cudaLaunchAttributeProgrammaticStreamSerialization;
    attrs[0].val.programmaticStreamSerializationAllowed = 1;
    cfg.attrs = attrs;
    cfg.numAttrs = 1;
    cudaLaunchKernelEx(&cfg, ql_final_kernel, out);
}